// round 17
// baseline (speedup 1.0000x reference)
#include <cuda_runtime.h>
#include <cuda_fp16.h>
#include <cstdint>

// ---------------- problem constants ----------------
#define MTOT 4096
#define NTOT 2048
#define KTOT 2048
#define BM   256
#define BN   128
#define BK   32
#define STAGES 8
#define KSTEPS (KTOT / BK)          // 64
#define THREADS 256
#define NBLOCKS 148                 // persistent CTAs; 194KB smem -> 1 CTA/SM
#define NUNIT (((MTOT + NTOT) * KTOT) / 32)  // 393216 convert units

// fp16 smem stage row: 32 halves = 64B, permuted so each thread's fragment is LDS.128
#define ROWB 64
#define ASTG_A (BM * ROWB)          // 16384 bytes per A stage (sized for big piece)
#define ASTG_B (BN * ROWB)          // 8192  bytes per B stage

// ---------------- smem layout (bytes) ----------------
#define SM_BIAS 0
#define SM_GNW  512
#define SM_GNB  1024
#define SM_A    2048
#define SM_B    (SM_A + STAGES * ASTG_A)          // 133120
#define SMEM_TOTAL (SM_B + STAGES * ASTG_B)       // 198656 (194KB), 1 CTA/SM

// ---------------- fp16, fragment-permuted scratch + grid barrier ----------------
__device__ __half g_xsh[(size_t)MTOT * KTOT];   // 16 MB
__device__ __half g_wsh[(size_t)NTOT * KTOT];   //  8 MB
__device__ unsigned int g_bar_count = 0;
__device__ unsigned int g_bar_gen   = 0;

// ---------------- PTX helpers ----------------
__device__ __forceinline__ uint32_t smem_u32(const void* p) {
    uint32_t a;
    asm("{ .reg .u64 t; cvta.to.shared.u64 t, %1; cvt.u32.u64 %0, t; }"
        : "=r"(a) : "l"(p));
    return a;
}

#define CP_A16I(smreg, gptr, smimm, gimm) \
    asm volatile("cp.async.cg.shared.global [%0+%2], [%1+%3], 16;" \
                 :: "r"(smreg), "l"(gptr), "n"(smimm), "n"(gimm) : "memory")
#define CP_COMMIT() asm volatile("cp.async.commit_group;" ::: "memory")
#define CP_WAIT(n)  asm volatile("cp.async.wait_group %0;" :: "n"(n) : "memory")

#define LDS128I(r0, r1, r2, r3, base, imm) \
    asm volatile("ld.shared.v4.u32 {%0, %1, %2, %3}, [%4+%5];" \
                 : "=r"(r0), "=r"(r1), "=r"(r2), "=r"(r3) : "r"(base), "n"(imm))

__device__ __forceinline__ void mma_f16(float* c, uint32_t a0, uint32_t a1,
                                        uint32_t a2, uint32_t a3,
                                        uint32_t b0, uint32_t b1) {
    asm volatile(
        "mma.sync.aligned.m16n8k16.row.col.f32.f16.f16.f32 "
        "{%0,%1,%2,%3}, {%4,%5,%6,%7}, {%8,%9}, {%0,%1,%2,%3};"
        : "+f"(c[0]), "+f"(c[1]), "+f"(c[2]), "+f"(c[3])
        : "r"(a0), "r"(a1), "r"(a2), "r"(a3), "r"(b0), "r"(b1));
}

#define GCH 262144
#define SCH 4096

// ================= templated tile worker: MI = 4 (256 rows) / 2 (128) / 1 (64) ======
template<int MI>
__device__ __forceinline__ void do_tile(
    char* smem, uint32_t sb, int row0, int bn,
    const float* __restrict__ bias, const float* __restrict__ gnw,
    const float* __restrict__ gnb, float* __restrict__ out,
    int tid, int wm, int wn, int gid, int tid4)
{
    float* bias_s = (float*)(smem + SM_BIAS);
    float* gnw_s  = (float*)(smem + SM_GNW);
    float* gnb_s  = (float*)(smem + SM_GNB);

    __syncthreads();                 // previous piece done with smem
    if (tid < BN) {
        bias_s[tid] = bias[bn * BN + tid];
        gnw_s[tid]  = gnw[bn * BN + tid];
        gnb_s[tid]  = gnb[bn * BN + tid];
    }

    int rA = tid >> 2, cA = tid & 3;
    uint32_t cpA = sb + SM_A + (uint32_t)(rA * ROWB + cA * 16);
    uint32_t cpB = sb + SM_B + (uint32_t)(rA * ROWB + cA * 16);
    const __half* aPtr = g_xsh + ((size_t)row0 + rA) * KTOT + cA * 8;
    const __half* bPtr = g_wsh + ((size_t)bn * BN + rA) * KTOT + cA * 8;

#define PRO_T(p) do {                                                             \
        CP_A16I(cpA, aPtr, (p) * ASTG_A + 0 * SCH, (p) * 64 + 0 * GCH);           \
        if constexpr (MI > 1)                                                     \
            CP_A16I(cpA, aPtr, (p) * ASTG_A + 1 * SCH, (p) * 64 + 1 * GCH);       \
        if constexpr (MI > 2) {                                                   \
            CP_A16I(cpA, aPtr, (p) * ASTG_A + 2 * SCH, (p) * 64 + 2 * GCH);       \
            CP_A16I(cpA, aPtr, (p) * ASTG_A + 3 * SCH, (p) * 64 + 3 * GCH);       \
        }                                                                         \
        CP_A16I(cpB, bPtr, (p) * ASTG_B + 0 * SCH, (p) * 64 + 0 * GCH);           \
        CP_A16I(cpB, bPtr, (p) * ASTG_B + 1 * SCH, (p) * 64 + 1 * GCH);           \
        CP_COMMIT();                                                              \
    } while (0)
    PRO_T(0); PRO_T(1); PRO_T(2); PRO_T(3); PRO_T(4); PRO_T(5); PRO_T(6);
#undef PRO_T
    aPtr += (STAGES - 1) * BK;
    bPtr += (STAGES - 1) * BK;

    float acc[MI][8][4];
#pragma unroll
    for (int mi = 0; mi < MI; mi++)
#pragma unroll
        for (int ni = 0; ni < 8; ni++)
#pragma unroll
            for (int j = 0; j < 4; j++) acc[mi][ni][j] = 0.f;

    uint32_t aBase = sb + SM_A + (uint32_t)((wm * (16 * MI) + gid) * ROWB + tid4 * 16);
    uint32_t bBase = sb + SM_B + (uint32_t)((wn * 64 + gid) * ROWB + tid4 * 16);

#define LD_FRAGS(S)                                                               \
        LDS128I(alo[0][0], alo[0][1], alo[0][2], alo[0][3], aBase,                \
                (S) * ASTG_A + 0 * 1024);                                         \
        LDS128I(ahi[0][0], ahi[0][1], ahi[0][2], ahi[0][3], aBase,                \
                (S) * ASTG_A + 0 * 1024 + 512);                                   \
        if constexpr (MI > 1) {                                                   \
            LDS128I(alo[1][0], alo[1][1], alo[1][2], alo[1][3], aBase,            \
                    (S) * ASTG_A + 1 * 1024);                                     \
            LDS128I(ahi[1][0], ahi[1][1], ahi[1][2], ahi[1][3], aBase,            \
                    (S) * ASTG_A + 1 * 1024 + 512);                               \
        }                                                                         \
        if constexpr (MI > 2) {                                                   \
            LDS128I(alo[2][0], alo[2][1], alo[2][2], alo[2][3], aBase,            \
                    (S) * ASTG_A + 2 * 1024);                                     \
            LDS128I(ahi[2][0], ahi[2][1], ahi[2][2], ahi[2][3], aBase,            \
                    (S) * ASTG_A + 2 * 1024 + 512);                               \
            LDS128I(alo[3][0], alo[3][1], alo[3][2], alo[3][3], aBase,            \
                    (S) * ASTG_A + 3 * 1024);                                     \
            LDS128I(ahi[3][0], ahi[3][1], ahi[3][2], ahi[3][3], aBase,            \
                    (S) * ASTG_A + 3 * 1024 + 512);                               \
        }                                                                         \
        LDS128I(bfr[0][0], bfr[0][1], bfr[0][2], bfr[0][3], bBase,                \
                (S) * ASTG_B + 0 * 512);                                          \
        LDS128I(bfr[1][0], bfr[1][1], bfr[1][2], bfr[1][3], bBase,                \
                (S) * ASTG_B + 1 * 512);                                          \
        LDS128I(bfr[2][0], bfr[2][1], bfr[2][2], bfr[2][3], bBase,                \
                (S) * ASTG_B + 2 * 512);                                          \
        LDS128I(bfr[3][0], bfr[3][1], bfr[3][2], bfr[3][3], bBase,                \
                (S) * ASTG_B + 3 * 512);                                          \
        LDS128I(bfr[4][0], bfr[4][1], bfr[4][2], bfr[4][3], bBase,                \
                (S) * ASTG_B + 4 * 512);                                          \
        LDS128I(bfr[5][0], bfr[5][1], bfr[5][2], bfr[5][3], bBase,                \
                (S) * ASTG_B + 5 * 512);                                          \
        LDS128I(bfr[6][0], bfr[6][1], bfr[6][2], bfr[6][3], bBase,                \
                (S) * ASTG_B + 6 * 512);                                          \
        LDS128I(bfr[7][0], bfr[7][1], bfr[7][2], bfr[7][3], bBase,                \
                (S) * ASTG_B + 7 * 512);

#define KITER(S)                                                                  \
    do {                                                                          \
        CP_WAIT(STAGES - 2);                                                      \
        __syncthreads();                                                          \
        if (k0 + (S) + STAGES - 1 < KSTEPS) {                                     \
            constexpr int PS = ((S) + STAGES - 1) & (STAGES - 1);                 \
            CP_A16I(cpA, aPtr, PS * ASTG_A + 0 * SCH, (S) * 64 + 0 * GCH);        \
            if constexpr (MI > 1)                                                 \
                CP_A16I(cpA, aPtr, PS * ASTG_A + 1 * SCH, (S) * 64 + 1 * GCH);    \
            if constexpr (MI > 2) {                                               \
                CP_A16I(cpA, aPtr, PS * ASTG_A + 2 * SCH, (S) * 64 + 2 * GCH);    \
                CP_A16I(cpA, aPtr, PS * ASTG_A + 3 * SCH, (S) * 64 + 3 * GCH);    \
            }                                                                     \
            CP_A16I(cpB, bPtr, PS * ASTG_B + 0 * SCH, (S) * 64 + 0 * GCH);        \
            CP_A16I(cpB, bPtr, PS * ASTG_B + 1 * SCH, (S) * 64 + 1 * GCH);        \
        }                                                                         \
        CP_COMMIT();                                                              \
        uint32_t alo[MI > 2 ? 4 : 2][4], ahi[MI > 2 ? 4 : 2][4], bfr[8][4];       \
        LD_FRAGS(S)                                                               \
        _Pragma("unroll")                                                         \
        for (int blk = 0; blk < 2; blk++)                                         \
            _Pragma("unroll")                                                     \
            for (int mi = 0; mi < MI; mi++)                                       \
                _Pragma("unroll")                                                 \
                for (int ni = 0; ni < 8; ni++)                                    \
                    mma_f16(acc[mi][ni],                                          \
                            alo[mi][blk * 2 + 0], ahi[mi][blk * 2 + 0],           \
                            alo[mi][blk * 2 + 1], ahi[mi][blk * 2 + 1],           \
                            bfr[ni][blk * 2 + 0], bfr[ni][blk * 2 + 1]);          \
    } while (0)

    for (int k0 = 0; k0 < KSTEPS; k0 += STAGES) {
        KITER(0);
        KITER(1);
        KITER(2);
        KITER(3);
        KITER(4);
        KITER(5);
        KITER(6);
        KITER(7);
        aPtr += STAGES * BK;
        bPtr += STAGES * BK;
    }
#undef KITER
#undef LD_FRAGS

    // ---- fused epilogue: bias + GroupNorm(64) + hardtanh ----
    int gcol = wn * 64;
    size_t gout = (size_t)bn * BN + gcol;

#pragma unroll
    for (int mi = 0; mi < MI; mi++) {
#pragma unroll
        for (int half = 0; half < 2; half++) {
            int row_l = wm * (16 * MI) + mi * 16 + half * 8 + gid;
            float sum = 0.f, ssq = 0.f;
            float v[8][2];
#pragma unroll
            for (int ni = 0; ni < 8; ni++) {
                int c = ni * 8 + 2 * tid4;
                float v0 = acc[mi][ni][half * 2 + 0] + bias_s[gcol + c + 0];
                float v1 = acc[mi][ni][half * 2 + 1] + bias_s[gcol + c + 1];
                v[ni][0] = v0; v[ni][1] = v1;
                sum += v0 + v1;
                ssq += v0 * v0 + v1 * v1;
            }
            sum += __shfl_xor_sync(0xffffffffu, sum, 1);
            ssq += __shfl_xor_sync(0xffffffffu, ssq, 1);
            sum += __shfl_xor_sync(0xffffffffu, sum, 2);
            ssq += __shfl_xor_sync(0xffffffffu, ssq, 2);

            float mean = sum * (1.f / 64.f);
            float var  = ssq * (1.f / 64.f) - mean * mean;
            float inv  = rsqrtf(var + 1e-5f);

            size_t orow = (size_t)(row0 + row_l) * NTOT + gout;
#pragma unroll
            for (int ni = 0; ni < 8; ni++) {
                int c = ni * 8 + 2 * tid4;
                float2 o;
                o.x = fminf(fmaxf((v[ni][0] - mean) * inv * gnw_s[gcol + c + 0]
                                  + gnb_s[gcol + c + 0], -1.f), 1.f);
                o.y = fminf(fmaxf((v[ni][1] - mean) * inv * gnw_s[gcol + c + 1]
                                  + gnb_s[gcol + c + 1], -1.f), 1.f);
                *(float2*)(out + orow + c) = o;
            }
        }
    }
}

// ---------------- kernel ----------------
__global__ void __launch_bounds__(THREADS, 1)
fused_linear_gn_ht_kernel(const float* __restrict__ x,
                          const float* __restrict__ w,
                          const float* __restrict__ bias,
                          const float* __restrict__ gnw,
                          const float* __restrict__ gnb,
                          float* __restrict__ out) {
    extern __shared__ char smem[];
    uint32_t sb = smem_u32(smem);
    int tid = threadIdx.x;
    int wid = tid >> 5, lid = tid & 31;
    int wm = wid >> 1, wn = wid & 1;
    int gid = lid >> 2, tid4 = lid & 3;
    int b = blockIdx.x;

    // ======== phase 1: fp32 -> fp16 convert + fragment permutation (grid-strided) ========
    for (int u = b * THREADS + tid; u < NUNIT; u += NBLOCKS * THREADS) {
        int row = u >> 6;
        int uc  = u & 63;
        const float* src;
        __half* dst;
        if (row < MTOT) {
            src = x + (size_t)row * KTOT + uc * 32;
            dst = g_xsh + (size_t)row * KTOT + uc * 32;
        } else {
            src = w + (size_t)(row - MTOT) * KTOT + uc * 32;
            dst = g_wsh + (size_t)(row - MTOT) * KTOT + uc * 32;
        }
        float v[32];
#pragma unroll
        for (int i = 0; i < 8; i++) {
            float4 f = ((const float4*)src)[i];
            v[i * 4 + 0] = f.x; v[i * 4 + 1] = f.y; v[i * 4 + 2] = f.z; v[i * 4 + 3] = f.w;
        }
        __half h[32];
#pragma unroll
        for (int t4 = 0; t4 < 4; t4++) {
#pragma unroll
            for (int blk = 0; blk < 2; blk++) {
                int o = t4 * 8 + blk * 4;
                int c = blk * 16 + 2 * t4;
                h[o + 0] = __float2half_rn(v[c + 0]);
                h[o + 1] = __float2half_rn(v[c + 1]);
                h[o + 2] = __float2half_rn(v[c + 8]);
                h[o + 3] = __float2half_rn(v[c + 9]);
            }
        }
#pragma unroll
        for (int i = 0; i < 4; i++)
            ((uint4*)dst)[i] = ((const uint4*)h)[i];
    }

    // ======== grid barrier (sense-reversal; monotonic gen across graph replays) ========
    __threadfence();
    __syncthreads();
    if (tid == 0) {
        unsigned my = atomicAdd(&g_bar_gen, 0u);
        if (atomicAdd(&g_bar_count, 1u) == NBLOCKS - 1u) {
            g_bar_count = 0u;
            __threadfence();
            atomicAdd(&g_bar_gen, 1u);
        } else {
            while (atomicAdd(&g_bar_gen, 0u) == my) { }
        }
    }
    __syncthreads();

    // ======== phase 2: heterogeneous piece schedule ========
    // 256 output positions (16 bm x 16 bn). Positions 0..147: big (256 rows, 1 CTA).
    // Positions 148..221: split into 2 halves (128 rows). Positions 222..255: 4 quarters (64 rows).
    // CTA b runs: big(b), half(148 + b/2, part b&1), quarter(222 + b/4, part b&3) [b<136].
    {
        int pos = b;
        do_tile<4>(smem, sb, (pos >> 4) * BM, pos & 15,
                   bias, gnw, gnb, out, tid, wm, wn, gid, tid4);
    }
    {
        int pos = 148 + (b >> 1);
        do_tile<2>(smem, sb, (pos >> 4) * BM + (b & 1) * 128, pos & 15,
                   bias, gnw, gnb, out, tid, wm, wn, gid, tid4);
    }
    if (b < 136) {
        int pos = 222 + (b >> 2);
        do_tile<1>(smem, sb, (pos >> 4) * BM + (b & 3) * 64, pos & 15,
                   bias, gnw, gnb, out, tid, wm, wn, gid, tid4);
    }
}

// ---------------- launch ----------------
extern "C" void kernel_launch(void* const* d_in, const int* in_sizes, int n_in,
                              void* d_out, int out_size) {
    const float* x    = (const float*)d_in[0];
    const float* w    = (const float*)d_in[1];
    const float* bias = (const float*)d_in[2];
    const float* gnw  = (const float*)d_in[3];
    const float* gnb  = (const float*)d_in[4];
    float* out = (float*)d_out;

    static bool attr_done = false;
    if (!attr_done) {
        cudaFuncSetAttribute(fused_linear_gn_ht_kernel,
                             cudaFuncAttributeMaxDynamicSharedMemorySize, SMEM_TOTAL);
        attr_done = true;
    }

    fused_linear_gn_ht_kernel<<<NBLOCKS, THREADS, SMEM_TOTAL>>>(x, w, bias, gnw, gnb, out);
}